// round 14
// baseline (speedup 1.0000x reference)
#include <cuda_runtime.h>
#include <cuda_bf16.h>

// SplineActivation: y[b][d] = sum_k Bspline_k(x[b][d]) * coeffs[d][k]
// Uniform cubic B-spline, branch-free truncated-power form:
//   t = 2x+2 in [0,4);  y(t) = P_0(t) + sum_{k=1..3} beta_k * ((t-k)+|t-k|)^3
// Async-bulk-store round: per-thread STG replaced by smem staging +
// cp.async.bulk.global.shared::cta (UBLKCP DMA). Writes leave as 1KB
// contiguous bursts per CTA-row, decoupled from warp scheduling; LSU only
// carries LDG+STS. Double-buffered 8-row stages with bulk_group tracking.
// Math/frame frozen from R8/R10: 2 dims/thread f32x2, persistent 1-wave
// grid, __ldcg loads.

#define INPUT_DIM 4096
#define BATCH_N   4096
#define TPB       128
#define GRID_Y    148
#define DP2       (INPUT_DIM / 2)      // 2048 column-pairs
#define RB        8                    // rows per stage

typedef unsigned long long u64;

__device__ __forceinline__ u64 pack2(float lo, float hi) {
    u64 r; asm("mov.b64 %0, {%1, %2};" : "=l"(r) : "f"(lo), "f"(hi)); return r;
}
__device__ __forceinline__ u64 fma2(u64 a, u64 b, u64 c) {
    u64 d; asm("fma.rn.f32x2 %0, %1, %2, %3;" : "=l"(d) : "l"(a), "l"(b), "l"(c)); return d;
}
__device__ __forceinline__ u64 mul2(u64 a, u64 b) {
    u64 d; asm("mul.rn.f32x2 %0, %1, %2;" : "=l"(d) : "l"(a), "l"(b)); return d;
}
__device__ __forceinline__ u64 add2(u64 a, u64 b) {
    u64 d; asm("add.rn.f32x2 %0, %1, %2;" : "=l"(d) : "l"(a), "l"(b)); return d;
}
__device__ __forceinline__ u64 abs2(u64 a) { return a & 0x7FFFFFFF7FFFFFFFULL; }

struct PairPoly { u64 A, B, C, D, b1, b2, b3; };   // lanes = the 2 dims

__device__ __forceinline__ u64 eval_pair(u64 x2, const PairPoly& q) {
    const u64 two2 = 0x4000000040000000ULL;   // {2,2}
    const u64 one2 = 0x3F8000003F800000ULL;   // {1,1}
    const u64 n1_2 = 0xBF800000BF800000ULL;   // {-1,-1}
    u64 t  = fma2(x2, two2, two2);            // 2x+2
    u64 r1 = fma2(x2, two2, one2);            // t-1
    u64 r2 = add2(x2, x2);                    // t-2
    u64 r3 = fma2(x2, two2, n1_2);            // t-3
    u64 p1 = add2(r1, abs2(r1));              // 2*(t-1)_+
    u64 p2 = add2(r2, abs2(r2));
    u64 p3 = add2(r3, abs2(r3));
    u64 h  = fma2(fma2(fma2(q.A, t, q.B), t, q.C), t, q.D);
    h = fma2(mul2(q.b1, p1), mul2(p1, p1), h);
    h = fma2(mul2(q.b2, p2), mul2(p2, p2), h);
    h = fma2(mul2(q.b3, p3), mul2(p3, p3), h);
    return h;
}

struct DimPoly { float A, B, C, D, b1, b2, b3; };

__device__ __forceinline__ float lead_coef(const float* e) {
    return fmaf(3.0f, e[1] - e[2], e[3] - e[0]);
}

__device__ __forceinline__ DimPoly build_dim(const float* e) {
    DimPoly q;
    float A0 = lead_coef(e + 0), A1 = lead_coef(e + 1);
    float A2 = lead_coef(e + 2), A3 = lead_coef(e + 3);
    q.A  = A0;
    q.B  = fmaf(-6.0f, e[1], 3.0f * (e[0] + e[2]));
    q.C  = 3.0f * (e[2] - e[0]);
    q.D  = fmaf(4.0f, e[1], e[0] + e[2]);
    q.b1 = (A1 - A0) * 0.125f;
    q.b2 = (A2 - A1) * 0.125f;
    q.b3 = (A3 - A2) * 0.125f;
    return q;
}

__global__ void __launch_bounds__(TPB)
spline_activation_kernel(const u64* __restrict__ x,
                         const float2* __restrict__ coeffs2,
                         u64* __restrict__ out) {
    // double-buffered staging: 2 stages x 8 rows x 1KB
    __shared__ u64 buf[2][RB][TPB];

    int tid = threadIdx.x;
    int dq2 = blockIdx.x * TPB + tid;                // 0..2047 column-pair

    // 14 coeffs (2 dims x 7), 8B-aligned.
    const float k6 = 1.0f / 6.0f;
    float c[14];
    const float2* cp = coeffs2 + (size_t)dq2 * 7;
#pragma unroll
    for (int i = 0; i < 7; ++i) {
        float2 v = __ldg(cp + i);
        c[2 * i + 0] = v.x * k6;
        c[2 * i + 1] = v.y * k6;
    }
    DimPoly s0 = build_dim(c), s1 = build_dim(c + 7);
    PairPoly q;
    q.A  = pack2(s0.A,  s1.A);
    q.B  = pack2(s0.B,  s1.B);
    q.C  = pack2(s0.C,  s1.C);
    q.D  = pack2(s0.D,  s1.D);
    q.b1 = pack2(s0.b1, s1.b1);
    q.b2 = pack2(s0.b2, s1.b2);
    q.b3 = pack2(s0.b3, s1.b3);

    // Persistent: rows r = blockIdx.y + GRID_Y * i.
    int row0 = blockIdx.y;
    int cnt  = (BATCH_N - row0 + GRID_Y - 1) / GRID_Y;     // 27 or 28
    const size_t STEP = (size_t)GRID_Y * DP2;              // row stride (u64)
    size_t idx = (size_t)row0 * DP2 + dq2;
    // CTA-contiguous gmem base for bulk stores (this CTA's 1KB row segment)
    size_t seg = (size_t)row0 * DP2 + (size_t)blockIdx.x * TPB;

    int i = 0, chunk = 0;
    for (; i + RB <= cnt; i += RB, ++chunk) {
        int stage = chunk & 1;

        // reuse guard: ensure the bulk group 2 chunks ago finished reading smem
        if (chunk >= 2) {
            if (tid == 0)
                asm volatile("cp.async.bulk.wait_group.read 1;" ::: "memory");
            __syncthreads();
        }

        // read burst: 8 independent LDG.64
        u64 a[RB];
#pragma unroll
        for (int k = 0; k < RB; ++k)
            a[k] = __ldcg(x + idx + (size_t)k * STEP);

        // compute into smem stage
#pragma unroll
        for (int k = 0; k < RB; ++k)
            buf[stage][k][tid] = eval_pair(a[k], q);

        asm volatile("fence.proxy.async.shared::cta;" ::: "memory");
        __syncthreads();

        // one thread launches 8 x 1KB bulk DMA stores
        if (tid == 0) {
#pragma unroll
            for (int k = 0; k < RB; ++k) {
                u64* gptr = out + seg + (size_t)k * STEP;
                unsigned saddr =
                    (unsigned)__cvta_generic_to_shared(&buf[stage][k][0]);
                asm volatile(
                    "cp.async.bulk.global.shared::cta.bulk_group [%0], [%1], %2;"
                    :: "l"(gptr), "r"(saddr), "r"(TPB * 8) : "memory");
            }
            asm volatile("cp.async.bulk.commit_group;" ::: "memory");
        }

        idx += (size_t)RB * STEP;
        seg += (size_t)RB * STEP;
    }

    // tail rows (3 or 4): plain streaming stores
    for (; i < cnt; ++i) {
        u64 a = __ldcg(x + idx);
        __stcs(out + idx, eval_pair(a, q));
        idx += STEP;
    }

    // drain all bulk stores before exit
    if (tid == 0)
        asm volatile("cp.async.bulk.wait_group 0;" ::: "memory");
}

extern "C" void kernel_launch(void* const* d_in, const int* in_sizes, int n_in,
                              void* d_out, int out_size) {
    const u64*    x      = (const u64*)d_in[0];      // (4096, 4096) fp32
    const float2* coeffs = (const float2*)d_in[1];   // (4096, 7) fp32
    u64*          out    = (u64*)d_out;              // (4096, 4096) fp32

    dim3 grid(DP2 / TPB, GRID_Y, 1);                 // (16, 148) = 2368 CTAs
    spline_activation_kernel<<<grid, TPB>>>(x, coeffs, out);
}

// round 15
// speedup vs baseline: 1.2926x; 1.2926x over previous
#include <cuda_runtime.h>
#include <cuda_bf16.h>

// SplineActivation: y[b][d] = sum_k Bspline_k(x[b][d]) * coeffs[d][k]
// Uniform cubic B-spline, branch-free truncated-power form:
//   t = 2x+2 in [0,4);  y(t) = P_0(t) + sum_{k=1..3} beta_k * ((t-k)+|t-k|)^3
// FINAL: R4-R14 establish the wall as DRAM mixed-stream bandwidth:
// 88MB/replay (64MB write drain + ~24MB structural x re-miss; per-replay L2
// traffic 128MB > 126MB L2, and write-no-allocate is unavailable — stcs/
// createpolicy/evict_first.v4/wt/bulk-DMA all inert) at ~4TB/s effective.
// Config = best-measured frame (R12 burst) tuned: RB=9 so the majority
// cnt=27 CTAs run exactly 3 read/write bursts with no scalar tail.
// 2 dims/thread f32x2 math, persistent 1-wave grid, __ldcg/__stcs.

#define INPUT_DIM 4096
#define BATCH_N   4096
#define TPB       128
#define GRID_Y    148
#define DP2       (INPUT_DIM / 2)      // 2048 column-pairs
#define RB        9                    // rows per read/write burst (27 = 3*9)

typedef unsigned long long u64;

__device__ __forceinline__ u64 pack2(float lo, float hi) {
    u64 r; asm("mov.b64 %0, {%1, %2};" : "=l"(r) : "f"(lo), "f"(hi)); return r;
}
__device__ __forceinline__ u64 fma2(u64 a, u64 b, u64 c) {
    u64 d; asm("fma.rn.f32x2 %0, %1, %2, %3;" : "=l"(d) : "l"(a), "l"(b), "l"(c)); return d;
}
__device__ __forceinline__ u64 mul2(u64 a, u64 b) {
    u64 d; asm("mul.rn.f32x2 %0, %1, %2;" : "=l"(d) : "l"(a), "l"(b)); return d;
}
__device__ __forceinline__ u64 add2(u64 a, u64 b) {
    u64 d; asm("add.rn.f32x2 %0, %1, %2;" : "=l"(d) : "l"(a), "l"(b)); return d;
}
__device__ __forceinline__ u64 abs2(u64 a) { return a & 0x7FFFFFFF7FFFFFFFULL; }

struct PairPoly { u64 A, B, C, D, b1, b2, b3; };   // lanes = the 2 dims

__device__ __forceinline__ u64 eval_pair(u64 x2, const PairPoly& q) {
    const u64 two2 = 0x4000000040000000ULL;   // {2,2}
    const u64 one2 = 0x3F8000003F800000ULL;   // {1,1}
    const u64 n1_2 = 0xBF800000BF800000ULL;   // {-1,-1}
    u64 t  = fma2(x2, two2, two2);            // 2x+2
    u64 r1 = fma2(x2, two2, one2);            // t-1
    u64 r2 = add2(x2, x2);                    // t-2
    u64 r3 = fma2(x2, two2, n1_2);            // t-3
    u64 p1 = add2(r1, abs2(r1));              // 2*(t-1)_+
    u64 p2 = add2(r2, abs2(r2));
    u64 p3 = add2(r3, abs2(r3));
    u64 h  = fma2(fma2(fma2(q.A, t, q.B), t, q.C), t, q.D);
    h = fma2(mul2(q.b1, p1), mul2(p1, p1), h);
    h = fma2(mul2(q.b2, p2), mul2(p2, p2), h);
    h = fma2(mul2(q.b3, p3), mul2(p3, p3), h);
    return h;
}

struct DimPoly { float A, B, C, D, b1, b2, b3; };

__device__ __forceinline__ float lead_coef(const float* e) {
    return fmaf(3.0f, e[1] - e[2], e[3] - e[0]);
}

__device__ __forceinline__ DimPoly build_dim(const float* e) {
    DimPoly q;
    float A0 = lead_coef(e + 0), A1 = lead_coef(e + 1);
    float A2 = lead_coef(e + 2), A3 = lead_coef(e + 3);
    q.A  = A0;
    q.B  = fmaf(-6.0f, e[1], 3.0f * (e[0] + e[2]));
    q.C  = 3.0f * (e[2] - e[0]);
    q.D  = fmaf(4.0f, e[1], e[0] + e[2]);
    q.b1 = (A1 - A0) * 0.125f;
    q.b2 = (A2 - A1) * 0.125f;
    q.b3 = (A3 - A2) * 0.125f;
    return q;
}

__global__ void __launch_bounds__(TPB)
spline_activation_kernel(const u64* __restrict__ x,
                         const float2* __restrict__ coeffs2,
                         u64* __restrict__ out) {
    int dq2 = blockIdx.x * TPB + threadIdx.x;        // 0..2047 column-pair

    // 14 coeffs (2 dims x 7), 8B-aligned.
    const float k6 = 1.0f / 6.0f;
    float c[14];
    const float2* cp = coeffs2 + (size_t)dq2 * 7;
#pragma unroll
    for (int i = 0; i < 7; ++i) {
        float2 v = __ldg(cp + i);
        c[2 * i + 0] = v.x * k6;
        c[2 * i + 1] = v.y * k6;
    }
    DimPoly s0 = build_dim(c), s1 = build_dim(c + 7);
    PairPoly q;
    q.A  = pack2(s0.A,  s1.A);
    q.B  = pack2(s0.B,  s1.B);
    q.C  = pack2(s0.C,  s1.C);
    q.D  = pack2(s0.D,  s1.D);
    q.b1 = pack2(s0.b1, s1.b1);
    q.b2 = pack2(s0.b2, s1.b2);
    q.b3 = pack2(s0.b3, s1.b3);

    // Persistent: rows r = blockIdx.y + GRID_Y * i.
    int row0 = blockIdx.y;
    int cnt  = (BATCH_N - row0 + GRID_Y - 1) / GRID_Y;     // 27 or 28
    const size_t STEP = (size_t)GRID_Y * DP2;              // row stride (u64)
    size_t idx = (size_t)row0 * DP2 + dq2;

    int i = 0;
    for (; i + RB <= cnt; i += RB) {
        u64 a[RB];
        // pure read burst: RB independent LDG.64 in flight
#pragma unroll
        for (int k = 0; k < RB; ++k)
            a[k] = __ldcg(x + idx + (size_t)k * STEP);
        // compute + streaming-store burst
#pragma unroll
        for (int k = 0; k < RB; ++k)
            __stcs(out + idx + (size_t)k * STEP, eval_pair(a[k], q));
        idx += (size_t)RB * STEP;
    }
    // tail (cnt=27 -> none, cnt=28 -> 1 row)
    for (; i < cnt; ++i) {
        u64 a = __ldcg(x + idx);
        __stcs(out + idx, eval_pair(a, q));
        idx += STEP;
    }
}

extern "C" void kernel_launch(void* const* d_in, const int* in_sizes, int n_in,
                              void* d_out, int out_size) {
    const u64*    x      = (const u64*)d_in[0];      // (4096, 4096) fp32
    const float2* coeffs = (const float2*)d_in[1];   // (4096, 7) fp32
    u64*          out    = (u64*)d_out;              // (4096, 4096) fp32

    dim3 grid(DP2 / TPB, GRID_Y, 1);                 // (16, 148) = 2368 CTAs
    spline_activation_kernel<<<grid, TPB>>>(x, coeffs, out);
}

// round 16
// speedup vs baseline: 1.4017x; 1.0844x over previous
#include <cuda_runtime.h>
#include <cuda_bf16.h>

// SplineActivation: y[b][d] = sum_k Bspline_k(x[b][d]) * coeffs[d][k]
// Uniform cubic B-spline, branch-free truncated-power form:
//   t = 2x+2 in [0,4);  y(t) = P_0(t) + sum_{k=1..3} beta_k * ((t-k)+|t-k|)^3
// Burst-specialization round: cnt is exactly 28 (row0<100) or 27. Emit both
// paths with compile-time burst sizes — 14+14 or 14+13 — fully unrolled,
// zero scalar tail rows, zero runtime predicates. Pure-read bursts of 14
// LDG.64 (3.5KB/warp in flight, +55% MLP vs R15's RB=9 which won 10%).
// 2 dims/thread f32x2 math, persistent 1-wave grid, __ldcg/__stcs.

#define INPUT_DIM 4096
#define BATCH_N   4096
#define TPB       128
#define GRID_Y    148
#define DP2       (INPUT_DIM / 2)      // 2048 column-pairs

typedef unsigned long long u64;

__device__ __forceinline__ u64 pack2(float lo, float hi) {
    u64 r; asm("mov.b64 %0, {%1, %2};" : "=l"(r) : "f"(lo), "f"(hi)); return r;
}
__device__ __forceinline__ u64 fma2(u64 a, u64 b, u64 c) {
    u64 d; asm("fma.rn.f32x2 %0, %1, %2, %3;" : "=l"(d) : "l"(a), "l"(b), "l"(c)); return d;
}
__device__ __forceinline__ u64 mul2(u64 a, u64 b) {
    u64 d; asm("mul.rn.f32x2 %0, %1, %2;" : "=l"(d) : "l"(a), "l"(b)); return d;
}
__device__ __forceinline__ u64 add2(u64 a, u64 b) {
    u64 d; asm("add.rn.f32x2 %0, %1, %2;" : "=l"(d) : "l"(a), "l"(b)); return d;
}
__device__ __forceinline__ u64 abs2(u64 a) { return a & 0x7FFFFFFF7FFFFFFFULL; }

struct PairPoly { u64 A, B, C, D, b1, b2, b3; };   // lanes = the 2 dims

__device__ __forceinline__ u64 eval_pair(u64 x2, const PairPoly& q) {
    const u64 two2 = 0x4000000040000000ULL;   // {2,2}
    const u64 one2 = 0x3F8000003F800000ULL;   // {1,1}
    const u64 n1_2 = 0xBF800000BF800000ULL;   // {-1,-1}
    u64 t  = fma2(x2, two2, two2);            // 2x+2
    u64 r1 = fma2(x2, two2, one2);            // t-1
    u64 r2 = add2(x2, x2);                    // t-2
    u64 r3 = fma2(x2, two2, n1_2);            // t-3
    u64 p1 = add2(r1, abs2(r1));              // 2*(t-1)_+
    u64 p2 = add2(r2, abs2(r2));
    u64 p3 = add2(r3, abs2(r3));
    u64 h  = fma2(fma2(fma2(q.A, t, q.B), t, q.C), t, q.D);
    h = fma2(mul2(q.b1, p1), mul2(p1, p1), h);
    h = fma2(mul2(q.b2, p2), mul2(p2, p2), h);
    h = fma2(mul2(q.b3, p3), mul2(p3, p3), h);
    return h;
}

struct DimPoly { float A, B, C, D, b1, b2, b3; };

__device__ __forceinline__ float lead_coef(const float* e) {
    return fmaf(3.0f, e[1] - e[2], e[3] - e[0]);
}

__device__ __forceinline__ DimPoly build_dim(const float* e) {
    DimPoly q;
    float A0 = lead_coef(e + 0), A1 = lead_coef(e + 1);
    float A2 = lead_coef(e + 2), A3 = lead_coef(e + 3);
    q.A  = A0;
    q.B  = fmaf(-6.0f, e[1], 3.0f * (e[0] + e[2]));
    q.C  = 3.0f * (e[2] - e[0]);
    q.D  = fmaf(4.0f, e[1], e[0] + e[2]);
    q.b1 = (A1 - A0) * 0.125f;
    q.b2 = (A2 - A1) * 0.125f;
    q.b3 = (A3 - A2) * 0.125f;
    return q;
}

template <int N>
__device__ __forceinline__ size_t burst(const u64* __restrict__ x,
                                        u64* __restrict__ out,
                                        size_t idx, size_t STEP,
                                        const PairPoly& q) {
    u64 a[N];
#pragma unroll
    for (int k = 0; k < N; ++k)                     // pure read burst
        a[k] = __ldcg(x + idx + (size_t)k * STEP);
#pragma unroll
    for (int k = 0; k < N; ++k)                     // compute + write burst
        __stcs(out + idx + (size_t)k * STEP, eval_pair(a[k], q));
    return idx + (size_t)N * STEP;
}

__global__ void __launch_bounds__(TPB)
spline_activation_kernel(const u64* __restrict__ x,
                         const float2* __restrict__ coeffs2,
                         u64* __restrict__ out) {
    int dq2 = blockIdx.x * TPB + threadIdx.x;        // 0..2047 column-pair

    // 14 coeffs (2 dims x 7), 8B-aligned.
    const float k6 = 1.0f / 6.0f;
    float c[14];
    const float2* cp = coeffs2 + (size_t)dq2 * 7;
#pragma unroll
    for (int i = 0; i < 7; ++i) {
        float2 v = __ldg(cp + i);
        c[2 * i + 0] = v.x * k6;
        c[2 * i + 1] = v.y * k6;
    }
    DimPoly s0 = build_dim(c), s1 = build_dim(c + 7);
    PairPoly q;
    q.A  = pack2(s0.A,  s1.A);
    q.B  = pack2(s0.B,  s1.B);
    q.C  = pack2(s0.C,  s1.C);
    q.D  = pack2(s0.D,  s1.D);
    q.b1 = pack2(s0.b1, s1.b1);
    q.b2 = pack2(s0.b2, s1.b2);
    q.b3 = pack2(s0.b3, s1.b3);

    // Persistent: rows r = blockIdx.y + GRID_Y * i.
    // BATCH_N = 27*GRID_Y + 100, so cnt = 28 iff row0 < 100, else 27.
    int row0 = blockIdx.y;
    const size_t STEP = (size_t)GRID_Y * DP2;              // row stride (u64)
    size_t idx = (size_t)row0 * DP2 + dq2;

    idx = burst<14>(x, out, idx, STEP, q);
    if (row0 < BATCH_N - 27 * GRID_Y)                      // cnt == 28
        burst<14>(x, out, idx, STEP, q);
    else                                                    // cnt == 27
        burst<13>(x, out, idx, STEP, q);
}

extern "C" void kernel_launch(void* const* d_in, const int* in_sizes, int n_in,
                              void* d_out, int out_size) {
    const u64*    x      = (const u64*)d_in[0];      // (4096, 4096) fp32
    const float2* coeffs = (const float2*)d_in[1];   // (4096, 7) fp32
    u64*          out    = (u64*)d_out;              // (4096, 4096) fp32

    dim3 grid(DP2 / TPB, GRID_Y, 1);                 // (16, 148) = 2368 CTAs
    spline_activation_kernel<<<grid, TPB>>>(x, coeffs, out);
}